// round 2
// baseline (speedup 1.0000x reference)
#include <cuda_runtime.h>

#define BB 4
#define RR 64
#define FF 1024
#define DD 128
#define FT 64          // f-tile width
#define NFT (FF/FT)    // 16 f-tiles

// ---------------- device scratch (static; no allocations) ----------------
__device__ float g_fproj[BB*FF*DD];          // frontier @ W1f            (2 MB)
__device__ float g_rproj[BB*RR*DD];          // robot @ W1r + b1
__device__ float g_wd[DD];                   // column sums of W1d
__device__ float g_escore[BB*RR*FF];         // exp(scores)               (1 MB)
__device__ float g_sums_part[NFT*BB*RR];     // per-ftile partial softmax sums
__device__ float g_msg_part[NFT*BB*RR*DD];   // per-ftile partial messages (2 MB)

// ---------------- kernel 1: projections -----------------------------------
// blocks 0..63 : f_proj  (b = blk>>4, ftile = blk&15), 64 rows each
// blocks 64..67: r_proj + b1 (b = blk-64), 64 rows
// block  68    : w_d column sums
#define K1_SMEM ((DD*DD + DD*68) * 4)

__global__ void k1_proj(const float* __restrict__ robot,
                        const float* __restrict__ frontier,
                        const float* __restrict__ W1,
                        const float* __restrict__ b1) {
    extern __shared__ float sm[];
    float* w_s = sm;               // 128*128
    float* x_s = sm + DD*DD;       // x transposed [k][row], stride 68
    const int t   = threadIdx.x;
    const int blk = blockIdx.x;

    if (blk >= 68) {
        if (t < DD) {
            float s = 0.f;
            #pragma unroll 8
            for (int k = 0; k < DD; k++) s += W1[(2*DD + k)*DD + t];
            g_wd[t] = s;
        }
        return;
    }

    const float* W;
    const float* X;
    float* O;
    bool add_b1;
    if (blk < 64) {
        int b = blk >> 4, ftile = blk & 15;
        W = W1 + DD*DD;                              // W1f rows
        X = frontier + (size_t)(b*FF + ftile*FT)*DD;
        O = g_fproj  + (size_t)(b*FF + ftile*FT)*DD;
        add_b1 = false;
    } else {
        int b = blk - 64;
        W = W1;                                      // W1r rows
        X = robot   + (size_t)(b*RR)*DD;
        O = g_rproj + (size_t)(b*RR)*DD;
        add_b1 = true;
    }

    for (int i = t; i < DD*DD; i += 256) w_s[i] = W[i];
    for (int i = t; i < 64*DD; i += 256) {
        int r = i >> 7, k = i & 127;
        x_s[k*68 + r] = X[i];
    }
    __syncthreads();

    const int cg = t & 15, rg = t >> 4;
    const int c0 = cg*8, r0 = rg*4;
    float acc[4][8];
    #pragma unroll
    for (int i = 0; i < 4; i++)
        #pragma unroll
        for (int j = 0; j < 8; j++) acc[i][j] = 0.f;

    #pragma unroll 4
    for (int k = 0; k < DD; k++) {
        float4 x4 = *(const float4*)&x_s[k*68 + r0];
        float4 wA = *(const float4*)&w_s[k*DD + c0];
        float4 wB = *(const float4*)&w_s[k*DD + c0 + 4];
        float xv[4] = {x4.x, x4.y, x4.z, x4.w};
        float wv[8] = {wA.x, wA.y, wA.z, wA.w, wB.x, wB.y, wB.z, wB.w};
        #pragma unroll
        for (int i = 0; i < 4; i++)
            #pragma unroll
            for (int j = 0; j < 8; j++)
                acc[i][j] = fmaf(xv[i], wv[j], acc[i][j]);
    }

    if (add_b1) {
        #pragma unroll
        for (int j = 0; j < 8; j++) {
            float bv = b1[c0 + j];
            #pragma unroll
            for (int i = 0; i < 4; i++) acc[i][j] += bv;
        }
    }

    #pragma unroll
    for (int i = 0; i < 4; i++) {
        *(float4*)&O[(r0+i)*DD + c0]     = make_float4(acc[i][0], acc[i][1], acc[i][2], acc[i][3]);
        *(float4*)&O[(r0+i)*DD + c0 + 4] = make_float4(acc[i][4], acc[i][5], acc[i][6], acc[i][7]);
    }
}

// ---------------- kernel 2: fused scores + exp + partial softmax + partial messages
// grid = 128: b = x>>5, ftile = (x>>1)&15, rhalf = x&1 (32 robots per block)
#define K2_SMEM_FLOATS (DD*36 + DD*68 + 32*65 + 64*132 + 64*36 + DD + DD + 32*16)
#define K2_SMEM (K2_SMEM_FLOATS * 4)

__global__ void k2_main(const float* __restrict__ frontier,
                        const float* __restrict__ geo,
                        const float* __restrict__ W2,
                        const float* __restrict__ b2) {
    extern __shared__ float sm[];
    float* rp_s  = sm;                   // [d][r]  128 x 36 (32 rows + pad)
    float* fp_s  = rp_s  + DD*36;        // [d][f]  128 x 68
    float* geo_s = fp_s  + DD*68;        // [r][f]   32 x 65
    float* fr_s  = geo_s + 32*65;        // [f][d]   64 x 132
    float* e_s   = fr_s  + 64*132;       // [f][r]   64 x 36
    float* wd_s  = e_s   + 64*36;        // 128
    float* w2_s  = wd_s  + DD;           // 128
    float* ps_s  = w2_s  + DD;           // 32 x 16 partial sums

    const int t = threadIdx.x;
    const int x = blockIdx.x;
    const int b     = x >> 5;
    const int ftile = (x >> 1) & 15;
    const int rbase = (x & 1) * 32;

    const float* RP = g_rproj + (size_t)(b*RR + rbase)*DD;
    for (int i = t; i < 32*DD; i += 256) { int r = i >> 7, d = i & 127; rp_s[d*36 + r] = RP[i]; }
    const float* FP = g_fproj + (size_t)(b*FF + ftile*FT)*DD;
    for (int i = t; i < FT*DD; i += 256) { int f = i >> 7, d = i & 127; fp_s[d*68 + f] = FP[i]; }
    const float* FR = frontier + (size_t)(b*FF + ftile*FT)*DD;
    for (int i = t; i < FT*DD; i += 256) { int f = i >> 7, d = i & 127; fr_s[f*132 + d] = FR[i]; }
    const float* G = geo + (size_t)(b*RR + rbase)*FF + ftile*FT;
    for (int i = t; i < 32*FT; i += 256) { int r = i >> 6, f = i & 63; geo_s[r*65 + f] = G[r*FF + f]; }
    if (t < DD) { wd_s[t] = g_wd[t]; w2_s[t] = W2[t]; }
    __syncthreads();

    // ---- phase A: scores (2r x 4f per thread over 32r x 64f) ----
    const int fx = t & 15, rx = t >> 4;
    const int f0 = fx*4,  r0 = rx*2;

    float gg[2][4];
    #pragma unroll
    for (int i = 0; i < 2; i++)
        #pragma unroll
        for (int j = 0; j < 4; j++)
            gg[i][j] = geo_s[(r0+i)*65 + f0 + j];

    float acc[2][4];
    #pragma unroll
    for (int i = 0; i < 2; i++)
        #pragma unroll
        for (int j = 0; j < 4; j++) acc[i][j] = 0.f;

    #pragma unroll 4
    for (int d = 0; d < DD; d++) {
        float2 rp2 = *(const float2*)&rp_s[d*36 + r0];
        float4 fp4 = *(const float4*)&fp_s[d*68 + f0];
        float wdv = wd_s[d], w2v = w2_s[d];
        float rpv[2] = {rp2.x, rp2.y};
        float fpv[4] = {fp4.x, fp4.y, fp4.z, fp4.w};
        #pragma unroll
        for (int i = 0; i < 2; i++)
            #pragma unroll
            for (int j = 0; j < 4; j++) {
                float v = rpv[i] + fpv[j];
                v = fmaf(gg[i][j], wdv, v);
                v = fmaxf(v, 0.f);
                acc[i][j] = fmaf(v, w2v, acc[i][j]);
            }
    }

    const float b2v = b2[0];
    float p0 = 0.f, p1 = 0.f;
    #pragma unroll
    for (int i = 0; i < 2; i++)
        #pragma unroll
        for (int j = 0; j < 4; j++) {
            float s = fmaxf(acc[i][j] + b2v, 0.f);
            float e = __expf(s);                // scores >= 0 and small: exact softmax w/o max-sub
            acc[i][j] = e;
            if (i == 0) p0 += e; else p1 += e;
            e_s[(f0+j)*36 + r0 + i] = e;
        }
    ps_s[(r0+0)*16 + fx] = p0;
    ps_s[(r0+1)*16 + fx] = p1;

    float* EO = g_escore + (size_t)(b*RR + rbase)*FF + ftile*FT;
    *(float4*)&EO[(r0+0)*FF + f0] = make_float4(acc[0][0], acc[0][1], acc[0][2], acc[0][3]);
    *(float4*)&EO[(r0+1)*FF + f0] = make_float4(acc[1][0], acc[1][1], acc[1][2], acc[1][3]);
    __syncthreads();

    if (t < 32) {
        float s = 0.f;
        #pragma unroll
        for (int q = 0; q < 16; q++) s += ps_s[t*16 + q];
        g_sums_part[ftile*(BB*RR) + b*RR + rbase + t] = s;
    }

    // ---- phase B: partial messages (2r x 8d per thread over 32r x 128d) ----
    const int dg = t & 15, rg2 = t >> 4;
    const int d0 = dg*8,  r1 = rg2*2;
    float m[2][8];
    #pragma unroll
    for (int i = 0; i < 2; i++)
        #pragma unroll
        for (int j = 0; j < 8; j++) m[i][j] = 0.f;

    #pragma unroll 2
    for (int f = 0; f < FT; f++) {
        float2 e2 = *(const float2*)&e_s[f*36 + r1];
        float4 fA = *(const float4*)&fr_s[f*132 + d0];
        float4 fB = *(const float4*)&fr_s[f*132 + d0 + 4];
        float ev[2] = {e2.x, e2.y};
        float fv[8] = {fA.x, fA.y, fA.z, fA.w, fB.x, fB.y, fB.z, fB.w};
        #pragma unroll
        for (int i = 0; i < 2; i++)
            #pragma unroll
            for (int j = 0; j < 8; j++)
                m[i][j] = fmaf(ev[i], fv[j], m[i][j]);
    }

    float* MO = g_msg_part + (size_t)(ftile*(BB*RR) + b*RR + rbase)*DD;
    #pragma unroll
    for (int i = 0; i < 2; i++) {
        *(float4*)&MO[(r1+i)*DD + d0]     = make_float4(m[i][0], m[i][1], m[i][2], m[i][3]);
        *(float4*)&MO[(r1+i)*DD + d0 + 4] = make_float4(m[i][4], m[i][5], m[i][6], m[i][7]);
    }
}

// ---------------- kernel 3: normalize + outputs ----------------------------
// grid = 256 (one per (b,r)), 128 threads
__global__ void k3_out(const float* __restrict__ robot,
                       const float* __restrict__ Wn,
                       const float* __restrict__ bn,
                       float* __restrict__ out) {
    __shared__ float comb[2*DD];
    const int br = blockIdx.x;
    const int t  = threadIdx.x;

    float s = 0.f;
    #pragma unroll
    for (int p = 0; p < NFT; p++) s += g_sums_part[p*(BB*RR) + br];
    const float inv = 1.0f / s;

    float mm = 0.f;
    #pragma unroll
    for (int p = 0; p < NFT; p++) mm += g_msg_part[(size_t)(p*(BB*RR) + br)*DD + t];
    comb[DD + t] = mm * inv;
    comb[t]      = robot[(size_t)br*DD + t];

    const float* E  = g_escore + (size_t)br*FF;
    float*       ew = out + (size_t)BB*RR*DD + (size_t)br*FF;
    #pragma unroll
    for (int k = 0; k < FF/DD; k++) ew[k*DD + t] = E[k*DD + t] * inv;
    __syncthreads();

    float acc = bn[t];
    #pragma unroll 8
    for (int k = 0; k < 2*DD; k++) acc = fmaf(comb[k], Wn[k*DD + t], acc);
    out[(size_t)br*DD + t] = fmaxf(acc, 0.f);
}

// ---------------- launch ----------------------------------------------------
extern "C" void kernel_launch(void* const* d_in, const int* in_sizes, int n_in,
                              void* d_out, int out_size) {
    const float* robot    = (const float*)d_in[0];
    const float* frontier = (const float*)d_in[1];
    const float* geo      = (const float*)d_in[2];
    const float* W1       = (const float*)d_in[3];
    const float* b1       = (const float*)d_in[4];
    const float* W2       = (const float*)d_in[5];
    const float* b2       = (const float*)d_in[6];
    const float* Wn       = (const float*)d_in[7];
    const float* bn       = (const float*)d_in[8];
    float* out = (float*)d_out;

    cudaFuncSetAttribute(k1_proj, cudaFuncAttributeMaxDynamicSharedMemorySize, K1_SMEM);
    cudaFuncSetAttribute(k2_main, cudaFuncAttributeMaxDynamicSharedMemorySize, K2_SMEM);

    k1_proj<<<69, 256, K1_SMEM>>>(robot, frontier, W1, b1);
    k2_main<<<128, 256, K2_SMEM>>>(frontier, geo, W2, b2);
    k3_out<<<256, 128>>>(robot, Wn, bn, out);
}